// round 2
// baseline (speedup 1.0000x reference)
#include <cuda_runtime.h>
#include <cstdint>

#define NTOK   4096
#define DMODEL 512
#define NHEADS 8
#define DHEAD  64
#define SCALEF 0.125f   // 1/sqrt(64)

// ---------------- scratch (static device globals; no allocation) ----------------
__device__ float g_qp[NTOK * DMODEL];
__device__ float g_kp[NTOK * DMODEL];
__device__ float g_vp[NTOK * DMODEL];
__device__ float g_ao[NTOK * DMODEL];
__device__ unsigned int g_maskbits[NTOK * (NTOK / 32)];
__device__ int g_mask_is_u8;

// ---------------- mask dtype detection + bit-packing ----------------
// bool masks may arrive as uint8 (1B) or widened (int32/float32). Detect by
// nonzero-byte density in the first 16 KB: u8 bool @10% true -> ~1638 nonzero
// bytes; int32/float32 -> ~410/~820. Threshold 1024.
__global__ void detect_mask_kernel(const unsigned char* __restrict__ mask) {
    __shared__ int cnt[256];
    int c = 0;
    for (int i = threadIdx.x; i < 16384; i += 256) c += (mask[i] != 0);
    cnt[threadIdx.x] = c;
    __syncthreads();
    for (int s = 128; s > 0; s >>= 1) {
        if (threadIdx.x < s) cnt[threadIdx.x] += cnt[threadIdx.x + s];
        __syncthreads();
    }
    if (threadIdx.x == 0) g_mask_is_u8 = (cnt[0] > 1024) ? 1 : 0;
}

__global__ void pack_mask_kernel(const void* __restrict__ maskp) {
    int w = blockIdx.x * blockDim.x + threadIdx.x;   // one 32-bit word of bits
    if (w >= NTOK * NTOK / 32) return;
    unsigned int bits = 0;
    if (g_mask_is_u8) {
        const unsigned char* m = (const unsigned char*)maskp + (size_t)w * 32;
        #pragma unroll
        for (int i = 0; i < 32; i++) bits |= (m[i] ? 1u : 0u) << i;
    } else {
        const unsigned int* m = (const unsigned int*)maskp + (size_t)w * 32;
        #pragma unroll
        for (int i = 0; i < 32; i++) bits |= (m[i] ? 1u : 0u) << i;
    }
    g_maskbits[w] = bits;
}

// ---------------- fp32 NT GEMM with bias: C[M,N] = X[M,K] @ W[N,K]^T + b ----------------
// 64x64 block tile, 256 threads, 4x4 microtile, K-step 16.
__global__ void gemm_nt_bias(const float* __restrict__ X, const float* __restrict__ W,
                             const float* __restrict__ bias, float* __restrict__ C,
                             int M, int Nout, int K) {
    __shared__ float Xs[16][68];
    __shared__ float Ws[16][68];
    int tid = threadIdx.x;
    int tx = tid & 15, ty = tid >> 4;
    int bm = blockIdx.y * 64, bn = blockIdx.x * 64;
    int r = tid >> 2;              // 0..63 row within tile
    int kq = (tid & 3) * 4;        // 0,4,8,12 k offset

    float acc[4][4];
    #pragma unroll
    for (int i = 0; i < 4; i++)
        #pragma unroll
        for (int j = 0; j < 4; j++) acc[i][j] = 0.f;

    for (int k0 = 0; k0 < K; k0 += 16) {
        float4 xv = *(const float4*)&X[(size_t)(bm + r) * K + k0 + kq];
        float4 wv = *(const float4*)&W[(size_t)(bn + r) * K + k0 + kq];
        Xs[kq + 0][r] = xv.x; Xs[kq + 1][r] = xv.y; Xs[kq + 2][r] = xv.z; Xs[kq + 3][r] = xv.w;
        Ws[kq + 0][r] = wv.x; Ws[kq + 1][r] = wv.y; Ws[kq + 2][r] = wv.z; Ws[kq + 3][r] = wv.w;
        __syncthreads();
        #pragma unroll
        for (int kk = 0; kk < 16; kk++) {
            float4 a = *(const float4*)&Xs[kk][ty * 4];
            float4 b = *(const float4*)&Ws[kk][tx * 4];
            acc[0][0] += a.x * b.x; acc[0][1] += a.x * b.y; acc[0][2] += a.x * b.z; acc[0][3] += a.x * b.w;
            acc[1][0] += a.y * b.x; acc[1][1] += a.y * b.y; acc[1][2] += a.y * b.z; acc[1][3] += a.y * b.w;
            acc[2][0] += a.z * b.x; acc[2][1] += a.z * b.y; acc[2][2] += a.z * b.z; acc[2][3] += a.z * b.w;
            acc[3][0] += a.w * b.x; acc[3][1] += a.w * b.y; acc[3][2] += a.w * b.z; acc[3][3] += a.w * b.w;
        }
        __syncthreads();
    }
    float4 bv = *(const float4*)&bias[bn + tx * 4];
    #pragma unroll
    for (int i = 0; i < 4; i++) {
        int mrow = bm + ty * 4 + i;
        float4 out;
        out.x = acc[i][0] + bv.x;
        out.y = acc[i][1] + bv.y;
        out.z = acc[i][2] + bv.z;
        out.w = acc[i][3] + bv.w;
        *(float4*)&C[(size_t)mrow * Nout + bn + tx * 4] = out;
    }
}

// ---------------- flash attention (fp32, online softmax) ----------------
// grid: (NTOK/64 q-blocks, NHEADS). 256 threads: tid = row*4 + c,
// row in [0,64), c in [0,4). Each thread owns 16 score cols (col = j*4+c)
// and 16 output dims (d = c*16 + i).
#define ATT_SMEM_FLOATS (64 * 64 + 3 * 64 * 68)
#define ATT_SMEM_BYTES  (ATT_SMEM_FLOATS * 4 + 128 * 4)

__global__ void attn_kernel(const float* __restrict__ QP, const float* __restrict__ KP,
                            const float* __restrict__ VP, float* __restrict__ O) {
    extern __shared__ float sm[];
    float* Qs = sm;                    // 64 x 64
    float* Ks = Qs + 64 * 64;          // 64 x 68 (padded)
    float* Vs = Ks + 64 * 68;          // 64 x 68
    float* Ps = Vs + 64 * 68;          // 64 x 68
    unsigned int* Mb = (unsigned int*)(Ps + 64 * 68);  // 64 rows x 2 words

    int tid = threadIdx.x;
    int row = tid >> 2;
    int c   = tid & 3;
    int h = blockIdx.y;
    int qbase = blockIdx.x * 64;

    // load Q tile (64 x 64)
    #pragma unroll
    for (int i = 0; i < 4; i++) {
        int f = tid + i * 256;
        int m = f >> 4;
        int dq = (f & 15) * 4;
        *(float4*)&Qs[m * 64 + dq] =
            *(const float4*)&QP[(size_t)(qbase + m) * DMODEL + h * DHEAD + dq];
    }

    float o[16];
    #pragma unroll
    for (int i = 0; i < 16; i++) o[i] = 0.f;
    float rmax = -3.0e38f, rsum = 0.f;

    for (int kb = 0; kb < NTOK / 64; ++kb) {
        int kbase = kb * 64;
        __syncthreads();   // previous tile's Vs/Ks fully consumed
        #pragma unroll
        for (int i = 0; i < 4; i++) {
            int f = tid + i * 256;
            int m = f >> 4;
            int dq = (f & 15) * 4;
            *(float4*)&Ks[m * 68 + dq] =
                *(const float4*)&KP[(size_t)(kbase + m) * DMODEL + h * DHEAD + dq];
            *(float4*)&Vs[m * 68 + dq] =
                *(const float4*)&VP[(size_t)(kbase + m) * DMODEL + h * DHEAD + dq];
        }
        if (tid < 128)
            Mb[tid] = g_maskbits[(size_t)(qbase + (tid >> 1)) * (NTOK / 32) + (kbase >> 5) + (tid & 1)];
        __syncthreads();

        // S = Q K^T for this thread's 16 columns
        float s[16];
        #pragma unroll
        for (int j = 0; j < 16; j++) s[j] = 0.f;
        #pragma unroll
        for (int d4 = 0; d4 < 16; ++d4) {
            float4 qv = *(const float4*)&Qs[row * 64 + d4 * 4];
            #pragma unroll
            for (int j = 0; j < 16; j++) {
                float4 kv = *(const float4*)&Ks[(j * 4 + c) * 68 + d4 * 4];
                s[j] += qv.x * kv.x + qv.y * kv.y + qv.z * kv.z + qv.w * kv.w;
            }
        }

        unsigned int m0 = Mb[row * 2], m1 = Mb[row * 2 + 1];
        float tmax = -3.0e38f;
        #pragma unroll
        for (int j = 0; j < 16; j++) {
            int col = j * 4 + c;
            unsigned int bits = (col < 32) ? m0 : m1;
            bool msk = (bits >> (col & 31)) & 1u;
            s[j] = msk ? -1.0e6f : s[j] * SCALEF;
            tmax = fmaxf(tmax, s[j]);
        }
        tmax = fmaxf(tmax, __shfl_xor_sync(0xffffffffu, tmax, 1));
        tmax = fmaxf(tmax, __shfl_xor_sync(0xffffffffu, tmax, 2));

        float nmax = fmaxf(rmax, tmax);
        float alpha = __expf(rmax - nmax);
        float lsum = 0.f;
        #pragma unroll
        for (int j = 0; j < 16; j++) {
            float p = __expf(s[j] - nmax);
            lsum += p;
            Ps[row * 68 + j * 4 + c] = p;
        }
        lsum += __shfl_xor_sync(0xffffffffu, lsum, 1);
        lsum += __shfl_xor_sync(0xffffffffu, lsum, 2);
        rsum = rsum * alpha + lsum;
        rmax = nmax;
        #pragma unroll
        for (int i = 0; i < 16; i++) o[i] *= alpha;
        __syncwarp();   // Ps visibility within the 4-lane row group

        // O += P V  (this thread: its row, dims c*16 .. c*16+15)
        #pragma unroll 4
        for (int j4 = 0; j4 < 16; ++j4) {
            float4 pv = *(const float4*)&Ps[row * 68 + j4 * 4];
            float pj[4] = {pv.x, pv.y, pv.z, pv.w};
            #pragma unroll
            for (int jj = 0; jj < 4; ++jj) {
                const float* vr = &Vs[(j4 * 4 + jj) * 68 + c * 16];
                float4 v0 = *(const float4*)&vr[0];
                float4 v1 = *(const float4*)&vr[4];
                float4 v2 = *(const float4*)&vr[8];
                float4 v3 = *(const float4*)&vr[12];
                float p = pj[jj];
                o[0]  += p * v0.x; o[1]  += p * v0.y; o[2]  += p * v0.z; o[3]  += p * v0.w;
                o[4]  += p * v1.x; o[5]  += p * v1.y; o[6]  += p * v1.z; o[7]  += p * v1.w;
                o[8]  += p * v2.x; o[9]  += p * v2.y; o[10] += p * v2.z; o[11] += p * v2.w;
                o[12] += p * v3.x; o[13] += p * v3.y; o[14] += p * v3.z; o[15] += p * v3.w;
            }
        }
    }

    float inv = 1.0f / rsum;
    size_t obase = (size_t)(qbase + row) * DMODEL + h * DHEAD + c * 16;
    #pragma unroll
    for (int q4 = 0; q4 < 4; q4++) {
        float4 out;
        out.x = o[q4 * 4 + 0] * inv;
        out.y = o[q4 * 4 + 1] * inv;
        out.z = o[q4 * 4 + 2] * inv;
        out.w = o[q4 * 4 + 3] * inv;
        *(float4*)&O[obase + q4 * 4] = out;
    }
}

// ---------------- launch ----------------
extern "C" void kernel_launch(void* const* d_in, const int* in_sizes, int n_in,
                              void* d_out, int out_size) {
    const float* q    = (const float*)d_in[0];
    const float* k    = (const float*)d_in[1];
    const float* v    = (const float*)d_in[2];
    const void*  mask = d_in[3];
    const float* wq_w = (const float*)d_in[4];
    const float* wq_b = (const float*)d_in[5];
    const float* wk_w = (const float*)d_in[6];
    const float* wk_b = (const float*)d_in[7];
    const float* wv_w = (const float*)d_in[8];
    const float* wv_b = (const float*)d_in[9];
    const float* wo_w = (const float*)d_in[10];
    const float* wo_b = (const float*)d_in[11];
    float* out = (float*)d_out;

    float *qp, *kp, *vp, *ao;
    cudaGetSymbolAddress((void**)&qp, g_qp);
    cudaGetSymbolAddress((void**)&kp, g_kp);
    cudaGetSymbolAddress((void**)&vp, g_vp);
    cudaGetSymbolAddress((void**)&ao, g_ao);

    cudaFuncSetAttribute(attn_kernel, cudaFuncAttributeMaxDynamicSharedMemorySize, ATT_SMEM_BYTES);

    // mask -> bitmask
    detect_mask_kernel<<<1, 256>>>((const unsigned char*)mask);
    pack_mask_kernel<<<(NTOK * NTOK / 32 + 255) / 256, 256>>>(mask);

    // projections
    dim3 ggrid(DMODEL / 64, NTOK / 64);
    gemm_nt_bias<<<ggrid, 256>>>(q, wq_w, wq_b, qp, NTOK, DMODEL, DMODEL);
    gemm_nt_bias<<<ggrid, 256>>>(k, wk_w, wk_b, kp, NTOK, DMODEL, DMODEL);
    gemm_nt_bias<<<ggrid, 256>>>(v, wv_w, wv_b, vp, NTOK, DMODEL, DMODEL);

    // attention
    attn_kernel<<<dim3(NTOK / 64, NHEADS), 256, ATT_SMEM_BYTES>>>(qp, kp, vp, ao);

    // output projection
    gemm_nt_bias<<<ggrid, 256>>>(ao, wo_w, wo_b, out, NTOK, DMODEL, DMODEL);
}

// round 4
// speedup vs baseline: 4.8729x; 4.8729x over previous
#include <cuda_runtime.h>
#include <cuda_bf16.h>
#include <cstdint>

#define NTOK   4096
#define DMODEL 512
#define NHEADS 8
#define DHEAD  64
#define SCALEF 0.125f   // 1/sqrt(64)

// ---------------- scratch (static device globals; no allocation) ----------------
__device__ float g_qp[NTOK * DMODEL];
__device__ float g_kp[NTOK * DMODEL];
__device__ float g_vp[NTOK * DMODEL];
__device__ float g_ao[NTOK * DMODEL];
__device__ __nv_bfloat16 g_qhi[NTOK * DMODEL];
__device__ __nv_bfloat16 g_qlo[NTOK * DMODEL];
__device__ __nv_bfloat16 g_khi[NTOK * DMODEL];
__device__ __nv_bfloat16 g_klo[NTOK * DMODEL];
__device__ __nv_bfloat16 g_vhi[NTOK * DMODEL];
__device__ __nv_bfloat16 g_vlo[NTOK * DMODEL];
__device__ unsigned int g_maskbits[NTOK * (NTOK / 32)];
__device__ int g_mask_is_u8;

// ---------------- mask dtype detection + bit-packing ----------------
__global__ void detect_mask_kernel(const unsigned char* __restrict__ mask) {
    __shared__ int cnt[256];
    int c = 0;
    for (int i = threadIdx.x; i < 16384; i += 256) c += (mask[i] != 0);
    cnt[threadIdx.x] = c;
    __syncthreads();
    for (int s = 128; s > 0; s >>= 1) {
        if (threadIdx.x < s) cnt[threadIdx.x] += cnt[threadIdx.x + s];
        __syncthreads();
    }
    if (threadIdx.x == 0) g_mask_is_u8 = (cnt[0] > 1024) ? 1 : 0;
}

__global__ void pack_mask_kernel(const void* __restrict__ maskp) {
    int w = blockIdx.x * blockDim.x + threadIdx.x;
    if (w >= NTOK * NTOK / 32) return;
    unsigned int bits = 0;
    if (g_mask_is_u8) {
        const unsigned char* m = (const unsigned char*)maskp + (size_t)w * 32;
        #pragma unroll
        for (int i = 0; i < 32; i++) bits |= (m[i] ? 1u : 0u) << i;
    } else {
        const unsigned int* m = (const unsigned int*)maskp + (size_t)w * 32;
        #pragma unroll
        for (int i = 0; i < 32; i++) bits |= (m[i] ? 1u : 0u) << i;
    }
    g_maskbits[w] = bits;
}

// ---------------- fp32 -> bf16 hi/lo split ----------------
__global__ void split_bf16_kernel(const float* __restrict__ src,
                                  __nv_bfloat16* __restrict__ hi,
                                  __nv_bfloat16* __restrict__ lo, int n) {
    int i = blockIdx.x * blockDim.x + threadIdx.x;
    if (i < n) {
        float x = src[i];
        __nv_bfloat16 h = __float2bfloat16(x);
        hi[i] = h;
        lo[i] = __float2bfloat16(x - __bfloat162float(h));
    }
}

// ---------------- fp32 NT GEMM with bias (projections) ----------------
__global__ void gemm_nt_bias(const float* __restrict__ X, const float* __restrict__ W,
                             const float* __restrict__ bias, float* __restrict__ C,
                             int M, int Nout, int K) {
    __shared__ float Xs[16][68];
    __shared__ float Ws[16][68];
    int tid = threadIdx.x;
    int tx = tid & 15, ty = tid >> 4;
    int bm = blockIdx.y * 64, bn = blockIdx.x * 64;
    int r = tid >> 2;
    int kq = (tid & 3) * 4;

    float acc[4][4];
    #pragma unroll
    for (int i = 0; i < 4; i++)
        #pragma unroll
        for (int j = 0; j < 4; j++) acc[i][j] = 0.f;

    for (int k0 = 0; k0 < K; k0 += 16) {
        float4 xv = *(const float4*)&X[(size_t)(bm + r) * K + k0 + kq];
        float4 wv = *(const float4*)&W[(size_t)(bn + r) * K + k0 + kq];
        Xs[kq + 0][r] = xv.x; Xs[kq + 1][r] = xv.y; Xs[kq + 2][r] = xv.z; Xs[kq + 3][r] = xv.w;
        Ws[kq + 0][r] = wv.x; Ws[kq + 1][r] = wv.y; Ws[kq + 2][r] = wv.z; Ws[kq + 3][r] = wv.w;
        __syncthreads();
        #pragma unroll
        for (int kk = 0; kk < 16; kk++) {
            float4 a = *(const float4*)&Xs[kk][ty * 4];
            float4 b = *(const float4*)&Ws[kk][tx * 4];
            acc[0][0] += a.x * b.x; acc[0][1] += a.x * b.y; acc[0][2] += a.x * b.z; acc[0][3] += a.x * b.w;
            acc[1][0] += a.y * b.x; acc[1][1] += a.y * b.y; acc[1][2] += a.y * b.z; acc[1][3] += a.y * b.w;
            acc[2][0] += a.z * b.x; acc[2][1] += a.z * b.y; acc[2][2] += a.z * b.z; acc[2][3] += a.z * b.w;
            acc[3][0] += a.w * b.x; acc[3][1] += a.w * b.y; acc[3][2] += a.w * b.z; acc[3][3] += a.w * b.w;
        }
        __syncthreads();
    }
    float4 bv = *(const float4*)&bias[bn + tx * 4];
    #pragma unroll
    for (int i = 0; i < 4; i++) {
        int mrow = bm + ty * 4 + i;
        float4 out;
        out.x = acc[i][0] + bv.x;
        out.y = acc[i][1] + bv.y;
        out.z = acc[i][2] + bv.z;
        out.w = acc[i][3] + bv.w;
        *(float4*)&C[(size_t)mrow * Nout + bn + tx * 4] = out;
    }
}

// ---------------- tensor-core flash attention ----------------
__device__ __forceinline__ uint32_t smaddr(const void* p) {
    return (uint32_t)__cvta_generic_to_shared(p);
}
__device__ __forceinline__ void ldsm_x4(uint32_t* r, uint32_t a) {
    asm volatile("ldmatrix.sync.aligned.m8n8.x4.shared.b16 {%0,%1,%2,%3}, [%4];"
                 : "=r"(r[0]), "=r"(r[1]), "=r"(r[2]), "=r"(r[3]) : "r"(a));
}
__device__ __forceinline__ void ldsm_x2(uint32_t* r, uint32_t a) {
    asm volatile("ldmatrix.sync.aligned.m8n8.x2.shared.b16 {%0,%1}, [%2];"
                 : "=r"(r[0]), "=r"(r[1]) : "r"(a));
}
__device__ __forceinline__ void ldsm_x2t(uint32_t* r, uint32_t a) {
    asm volatile("ldmatrix.sync.aligned.m8n8.x2.trans.shared.b16 {%0,%1}, [%2];"
                 : "=r"(r[0]), "=r"(r[1]) : "r"(a));
}
__device__ __forceinline__ void mma_bf16(float* d, const uint32_t* a, const uint32_t* b) {
    asm volatile("mma.sync.aligned.m16n8k16.row.col.f32.bf16.bf16.f32 "
                 "{%0,%1,%2,%3}, {%4,%5,%6,%7}, {%8,%9}, {%0,%1,%2,%3};"
                 : "+f"(d[0]), "+f"(d[1]), "+f"(d[2]), "+f"(d[3])
                 : "r"(a[0]), "r"(a[1]), "r"(a[2]), "r"(a[3]), "r"(b[0]), "r"(b[1]));
}
__device__ __forceinline__ uint32_t pack_bf16(__nv_bfloat16 a, __nv_bfloat16 b) {
    return (uint32_t)__bfloat16_as_ushort(a) | ((uint32_t)__bfloat16_as_ushort(b) << 16);
}
__device__ __forceinline__ void split_pack(float x, float y, uint32_t& hi, uint32_t& lo) {
    __nv_bfloat16 hx = __float2bfloat16(x), hy = __float2bfloat16(y);
    __nv_bfloat16 lx = __float2bfloat16(x - __bfloat162float(hx));
    __nv_bfloat16 ly = __float2bfloat16(y - __bfloat162float(hy));
    hi = pack_bf16(hx, hy);
    lo = pack_bf16(lx, ly);
}

#define SROW 72   // smem row stride in bf16 elems (144B -> conflict-free LDSM)

// CTA: 128 q-rows x 1 head, 8 warps, each warp = 16 q-rows x full 64 kv width.
__global__ __launch_bounds__(256, 1) void attn_mma_kernel(
    const __nv_bfloat16* __restrict__ Qhi_g, const __nv_bfloat16* __restrict__ Qlo_g,
    const __nv_bfloat16* __restrict__ Khi_g, const __nv_bfloat16* __restrict__ Klo_g,
    const __nv_bfloat16* __restrict__ Vhi_g, const __nv_bfloat16* __restrict__ Vlo_g,
    float* __restrict__ AO)
{
    __shared__ __nv_bfloat16 sm[18432];   // Q-stage (2x128xSROW) OR K/V tiles (4x64xSROW)
    __shared__ uint32_t Mb[256];          // 128 rows x 2 mask words

    int tid = threadIdx.x;
    int lane = tid & 31, wid = tid >> 5;
    int g = lane >> 2, t = lane & 3;
    int h = blockIdx.y;
    int qbase = blockIdx.x * 128;
    int qr0 = wid * 16;

    // ---- stage Q tile (hi/lo planes), 2048 uint4 ----
    #pragma unroll
    for (int i = 0; i < 8; i++) {
        int u = tid + i * 256;
        int pl = u >> 10;
        int r = (u >> 3) & 127;
        int c8 = (u & 7) * 8;
        const __nv_bfloat16* src = pl ? Qlo_g : Qhi_g;
        uint4 val = *(const uint4*)&src[(size_t)(qbase + r) * DMODEL + h * DHEAD + c8];
        *(uint4*)&sm[pl * 9216 + r * SROW + c8] = val;
    }
    __syncthreads();

    // ---- Q A-fragments into registers (4 k-steps, hi+lo) ----
    uint32_t qh[4][4], ql[4][4];
    {
        int lrow = qr0 + (lane & 15);
        int lcol = (lane < 16) ? 0 : 8;
        #pragma unroll
        for (int ks = 0; ks < 4; ks++) {
            ldsm_x4(qh[ks], smaddr(&sm[lrow * SROW + ks * 16 + lcol]));
            ldsm_x4(ql[ks], smaddr(&sm[9216 + lrow * SROW + ks * 16 + lcol]));
        }
    }

    float o[8][4];
    #pragma unroll
    for (int i = 0; i < 8; i++)
        #pragma unroll
        for (int j = 0; j < 4; j++) o[i][j] = 0.f;
    float rmax0 = -3.0e38f, rmax1 = -3.0e38f, rsum0 = 0.f, rsum1 = 0.f;

    __nv_bfloat16* Khi = sm;
    __nv_bfloat16* Klo = sm + 4608;
    __nv_bfloat16* Vhi = sm + 9216;
    __nv_bfloat16* Vlo = sm + 13824;
    int l15 = lane & 15;
    int krow = l15 & 7;
    int kcsel = (l15 >> 3) * 8;

    for (int kb = 0; kb < NTOK / 64; kb++) {
        int kbase = kb * 64;
        __syncthreads();   // previous tile fully consumed (and Q-frag reads done)
        #pragma unroll
        for (int i = 0; i < 8; i++) {
            int u = tid + i * 256;
            int pl = u >> 9;
            int r = (u >> 3) & 63;
            int c8 = (u & 7) * 8;
            const __nv_bfloat16* src = (pl == 0) ? Khi_g : (pl == 1) ? Klo_g
                                     : (pl == 2) ? Vhi_g : Vlo_g;
            uint4 val = *(const uint4*)&src[(size_t)(kbase + r) * DMODEL + h * DHEAD + c8];
            *(uint4*)&sm[pl * 4608 + r * SROW + c8] = val;
        }
        Mb[tid] = g_maskbits[(size_t)(qbase + (tid >> 1)) * (NTOK / 32) + kb * 2 + (tid & 1)];
        __syncthreads();

        // ---- S = Q K^T (split bf16: 3 MMAs per tile-product) ----
        float s[8][4];
        #pragma unroll
        for (int i = 0; i < 8; i++)
            #pragma unroll
            for (int j = 0; j < 4; j++) s[i][j] = 0.f;
        #pragma unroll
        for (int ks = 0; ks < 4; ks++) {
            #pragma unroll
            for (int nt = 0; nt < 8; nt++) {
                uint32_t bh[2], bl[2];
                ldsm_x2(bh, smaddr(&Khi[(nt * 8 + krow) * SROW + ks * 16 + kcsel]));
                ldsm_x2(bl, smaddr(&Klo[(nt * 8 + krow) * SROW + ks * 16 + kcsel]));
                mma_bf16(s[nt], qh[ks], bh);
                mma_bf16(s[nt], ql[ks], bh);
                mma_bf16(s[nt], qh[ks], bl);
            }
        }

        // ---- mask + scale + online softmax ----
        uint32_t m00 = Mb[(qr0 + g) * 2],     m01 = Mb[(qr0 + g) * 2 + 1];
        uint32_t m10 = Mb[(qr0 + g + 8) * 2], m11 = Mb[(qr0 + g + 8) * 2 + 1];
        float mx0 = -3.0e38f, mx1 = -3.0e38f;
        #pragma unroll
        for (int nt = 0; nt < 8; nt++) {
            int c0 = nt * 8 + 2 * t;
            uint32_t w0 = (c0 < 32) ? m00 : m01;
            uint32_t w1 = (c0 < 32) ? m10 : m11;
            int sh = c0 & 31;
            s[nt][0] = ((w0 >> sh) & 1u)       ? -1.0e6f : s[nt][0] * SCALEF;
            s[nt][1] = ((w0 >> (sh + 1)) & 1u) ? -1.0e6f : s[nt][1] * SCALEF;
            s[nt][2] = ((w1 >> sh) & 1u)       ? -1.0e6f : s[nt][2] * SCALEF;
            s[nt][3] = ((w1 >> (sh + 1)) & 1u) ? -1.0e6f : s[nt][3] * SCALEF;
            mx0 = fmaxf(mx0, fmaxf(s[nt][0], s[nt][1]));
            mx1 = fmaxf(mx1, fmaxf(s[nt][2], s[nt][3]));
        }
        mx0 = fmaxf(mx0, __shfl_xor_sync(0xffffffffu, mx0, 1));
        mx0 = fmaxf(mx0, __shfl_xor_sync(0xffffffffu, mx0, 2));
        mx1 = fmaxf(mx1, __shfl_xor_sync(0xffffffffu, mx1, 1));
        mx1 = fmaxf(mx1, __shfl_xor_sync(0xffffffffu, mx1, 2));

        float nm0 = fmaxf(rmax0, mx0), nm1 = fmaxf(rmax1, mx1);
        float al0 = __expf(rmax0 - nm0), al1 = __expf(rmax1 - nm1);
        rmax0 = nm0; rmax1 = nm1;
        float ls0 = 0.f, ls1 = 0.f;
        #pragma unroll
        for (int nt = 0; nt < 8; nt++) {
            float p0 = __expf(s[nt][0] - nm0);
            float p1 = __expf(s[nt][1] - nm0);
            float p2 = __expf(s[nt][2] - nm1);
            float p3 = __expf(s[nt][3] - nm1);
            s[nt][0] = p0; s[nt][1] = p1; s[nt][2] = p2; s[nt][3] = p3;
            ls0 += p0 + p1; ls1 += p2 + p3;
        }
        ls0 += __shfl_xor_sync(0xffffffffu, ls0, 1);
        ls0 += __shfl_xor_sync(0xffffffffu, ls0, 2);
        ls1 += __shfl_xor_sync(0xffffffffu, ls1, 1);
        ls1 += __shfl_xor_sync(0xffffffffu, ls1, 2);
        rsum0 = rsum0 * al0 + ls0;
        rsum1 = rsum1 * al1 + ls1;
        #pragma unroll
        for (int nt = 0; nt < 8; nt++) {
            o[nt][0] *= al0; o[nt][1] *= al0; o[nt][2] *= al1; o[nt][3] *= al1;
        }

        // ---- O += P V : P A-frags straight from S accumulators (register reuse) ----
        #pragma unroll
        for (int ks = 0; ks < 4; ks++) {
            uint32_t pah[4], pal[4];
            split_pack(s[2 * ks][0],     s[2 * ks][1],     pah[0], pal[0]);
            split_pack(s[2 * ks][2],     s[2 * ks][3],     pah[1], pal[1]);
            split_pack(s[2 * ks + 1][0], s[2 * ks + 1][1], pah[2], pal[2]);
            split_pack(s[2 * ks + 1][2], s[2 * ks + 1][3], pah[3], pal[3]);
            int vrow = ks * 16 + l15;
            #pragma unroll
            for (int ntd = 0; ntd < 8; ntd++) {
                uint32_t vh[2], vl[2];
                ldsm_x2t(vh, smaddr(&Vhi[vrow * SROW + ntd * 8]));
                ldsm_x2t(vl, smaddr(&Vlo[vrow * SROW + ntd * 8]));
                mma_bf16(o[ntd], pah, vh);
                mma_bf16(o[ntd], pal, vh);
                mma_bf16(o[ntd], pah, vl);
            }
        }
    }

    // ---- epilogue ----
    float inv0 = 1.0f / rsum0, inv1 = 1.0f / rsum1;
    int r0 = qbase + qr0 + g;
    #pragma unroll
    for (int nt = 0; nt < 8; nt++) {
        int c = h * DHEAD + nt * 8 + 2 * t;
        float2 a; a.x = o[nt][0] * inv0; a.y = o[nt][1] * inv0;
        *(float2*)&AO[(size_t)r0 * DMODEL + c] = a;
        float2 b; b.x = o[nt][2] * inv1; b.y = o[nt][3] * inv1;
        *(float2*)&AO[(size_t)(r0 + 8) * DMODEL + c] = b;
    }
}

// ---------------- launch ----------------
extern "C" void kernel_launch(void* const* d_in, const int* in_sizes, int n_in,
                              void* d_out, int out_size) {
    const float* q    = (const float*)d_in[0];
    const float* k    = (const float*)d_in[1];
    const float* v    = (const float*)d_in[2];
    const void*  mask = d_in[3];
    const float* wq_w = (const float*)d_in[4];
    const float* wq_b = (const float*)d_in[5];
    const float* wk_w = (const float*)d_in[6];
    const float* wk_b = (const float*)d_in[7];
    const float* wv_w = (const float*)d_in[8];
    const float* wv_b = (const float*)d_in[9];
    const float* wo_w = (const float*)d_in[10];
    const float* wo_b = (const float*)d_in[11];
    float* out = (float*)d_out;

    float *qp, *kp, *vp, *ao;
    cudaGetSymbolAddress((void**)&qp, g_qp);
    cudaGetSymbolAddress((void**)&kp, g_kp);
    cudaGetSymbolAddress((void**)&vp, g_vp);
    cudaGetSymbolAddress((void**)&ao, g_ao);
    __nv_bfloat16 *qhi, *qlo, *khi, *klo, *vhi, *vlo;
    cudaGetSymbolAddress((void**)&qhi, g_qhi);
    cudaGetSymbolAddress((void**)&qlo, g_qlo);
    cudaGetSymbolAddress((void**)&khi, g_khi);
    cudaGetSymbolAddress((void**)&klo, g_klo);
    cudaGetSymbolAddress((void**)&vhi, g_vhi);
    cudaGetSymbolAddress((void**)&vlo, g_vlo);

    // mask -> bitmask
    detect_mask_kernel<<<1, 256>>>((const unsigned char*)mask);
    pack_mask_kernel<<<(NTOK * NTOK / 32 + 255) / 256, 256>>>(mask);

    // projections (fp32)
    dim3 ggrid(DMODEL / 64, NTOK / 64);
    gemm_nt_bias<<<ggrid, 256>>>(q, wq_w, wq_b, qp, NTOK, DMODEL, DMODEL);
    gemm_nt_bias<<<ggrid, 256>>>(k, wk_w, wk_b, kp, NTOK, DMODEL, DMODEL);
    gemm_nt_bias<<<ggrid, 256>>>(v, wv_w, wv_b, vp, NTOK, DMODEL, DMODEL);

    // split to bf16 hi/lo planes
    int n = NTOK * DMODEL;
    split_bf16_kernel<<<(n + 255) / 256, 256>>>(qp, qhi, qlo, n);
    split_bf16_kernel<<<(n + 255) / 256, 256>>>(kp, khi, klo, n);
    split_bf16_kernel<<<(n + 255) / 256, 256>>>(vp, vhi, vlo, n);

    // tensor-core attention
    attn_mma_kernel<<<dim3(NTOK / 128, NHEADS), 256>>>(qhi, qlo, khi, klo, vhi, vlo, ao);

    // output projection (fp32)
    gemm_nt_bias<<<ggrid, 256>>>(ao, wo_w, wo_b, out, NTOK, DMODEL, DMODEL);
}

// round 6
// speedup vs baseline: 9.4903x; 1.9476x over previous
#include <cuda_runtime.h>
#include <cuda_bf16.h>
#include <cuda_fp16.h>
#include <cstdint>

#define NTOK   4096
#define DMODEL 512
#define NHEADS 8
#define DHEAD  64
#define SCALEF 0.125f   // 1/sqrt(64)

// ---------------- scratch (static device globals; no allocation) ----------------
__device__ __half g_q16[NTOK * DMODEL];
__device__ __half g_k16[NTOK * DMODEL];
__device__ __half g_v16[NTOK * DMODEL];
__device__ __nv_bfloat16 g_aohi[NTOK * DMODEL];
__device__ __nv_bfloat16 g_aolo[NTOK * DMODEL];
__device__ unsigned int g_maskbits[NTOK * (NTOK / 32)];
__device__ int g_mask_is_u8;

// ---------------- mask dtype detection + bit-packing ----------------
__global__ void detect_mask_kernel(const unsigned char* __restrict__ mask) {
    __shared__ int cnt[256];
    int c = 0;
    for (int i = threadIdx.x; i < 16384; i += 256) c += (mask[i] != 0);
    cnt[threadIdx.x] = c;
    __syncthreads();
    for (int s = 128; s > 0; s >>= 1) {
        if (threadIdx.x < s) cnt[threadIdx.x] += cnt[threadIdx.x + s];
        __syncthreads();
    }
    if (threadIdx.x == 0) g_mask_is_u8 = (cnt[0] > 1024) ? 1 : 0;
}

__global__ void pack_mask_kernel(const void* __restrict__ maskp) {
    int w = blockIdx.x * blockDim.x + threadIdx.x;
    if (w >= NTOK * NTOK / 32) return;
    unsigned int bits = 0;
    if (g_mask_is_u8) {
        const unsigned char* m = (const unsigned char*)maskp + (size_t)w * 32;
        #pragma unroll
        for (int i = 0; i < 32; i++) bits |= (m[i] ? 1u : 0u) << i;
    } else {
        const unsigned int* m = (const unsigned int*)maskp + (size_t)w * 32;
        #pragma unroll
        for (int i = 0; i < 32; i++) bits |= (m[i] ? 1u : 0u) << i;
    }
    g_maskbits[w] = bits;
}

// ---------------- MMA / LDSM helpers ----------------
__device__ __forceinline__ uint32_t smaddr(const void* p) {
    return (uint32_t)__cvta_generic_to_shared(p);
}
__device__ __forceinline__ void ldsm_x4(uint32_t* r, uint32_t a) {
    asm volatile("ldmatrix.sync.aligned.m8n8.x4.shared.b16 {%0,%1,%2,%3}, [%4];"
                 : "=r"(r[0]), "=r"(r[1]), "=r"(r[2]), "=r"(r[3]) : "r"(a));
}
__device__ __forceinline__ void ldsm_x2(uint32_t* r, uint32_t a) {
    asm volatile("ldmatrix.sync.aligned.m8n8.x2.shared.b16 {%0,%1}, [%2];"
                 : "=r"(r[0]), "=r"(r[1]) : "r"(a));
}
__device__ __forceinline__ void ldsm_x2t(uint32_t* r, uint32_t a) {
    asm volatile("ldmatrix.sync.aligned.m8n8.x2.trans.shared.b16 {%0,%1}, [%2];"
                 : "=r"(r[0]), "=r"(r[1]) : "r"(a));
}
__device__ __forceinline__ void mma_bf16(float* d, const uint32_t* a, const uint32_t* b) {
    asm volatile("mma.sync.aligned.m16n8k16.row.col.f32.bf16.bf16.f32 "
                 "{%0,%1,%2,%3}, {%4,%5,%6,%7}, {%8,%9}, {%0,%1,%2,%3};"
                 : "+f"(d[0]), "+f"(d[1]), "+f"(d[2]), "+f"(d[3])
                 : "r"(a[0]), "r"(a[1]), "r"(a[2]), "r"(a[3]), "r"(b[0]), "r"(b[1]));
}
__device__ __forceinline__ void mma_f16(float* d, const uint32_t* a, const uint32_t* b) {
    asm volatile("mma.sync.aligned.m16n8k16.row.col.f32.f16.f16.f32 "
                 "{%0,%1,%2,%3}, {%4,%5,%6,%7}, {%8,%9}, {%0,%1,%2,%3};"
                 : "+f"(d[0]), "+f"(d[1]), "+f"(d[2]), "+f"(d[3])
                 : "r"(a[0]), "r"(a[1]), "r"(a[2]), "r"(a[3]), "r"(b[0]), "r"(b[1]));
}
__device__ __forceinline__ uint32_t pack_h2(float x, float y) {
    __half2 p = __floats2half2_rn(x, y);
    return *reinterpret_cast<uint32_t*>(&p);
}
__device__ __forceinline__ uint32_t pack_bf2(__nv_bfloat16 a, __nv_bfloat16 b) {
    return (uint32_t)__bfloat16_as_ushort(a) | ((uint32_t)__bfloat16_as_ushort(b) << 16);
}

#define CP_ASYNC16(dst, src) \
    asm volatile("cp.async.cg.shared.global [%0], [%1], 16;" :: "r"(dst), "l"(src))
#define CP_COMMIT() asm volatile("cp.async.commit_group;")
#define CP_WAIT1()  asm volatile("cp.async.wait_group 1;")
#define CP_WAIT0()  asm volatile("cp.async.wait_group 0;")

// ---------------- tensor-core split-bf16 GEMM: C = X[M,K] @ W[N,K]^T + b ----------------
#define GK 32      // k-chunk
#define GSR 40     // smem row stride (bf16), 80B -> 16B-aligned + conflict-free

template<bool PRESPLIT, bool OUTF32>
__global__ __launch_bounds__(256) void gemm_tc(
    const float* __restrict__ Xf,
    const __nv_bfloat16* __restrict__ Xhi_g, const __nv_bfloat16* __restrict__ Xlo_g,
    const float* __restrict__ W, const float* __restrict__ bias, void* __restrict__ outp)
{
    __shared__ __nv_bfloat16 Xh[128 * GSR], Xl[128 * GSR];
    __shared__ __nv_bfloat16 Wh[64 * GSR],  Wl[64 * GSR];

    int tid = threadIdx.x;
    int lane = tid & 31, wid = tid >> 5;
    int g = lane >> 2, t = lane & 3;
    int bm = blockIdx.y * 128, bn = blockIdx.x * 64;

    int lrow = wid * 16 + (lane & 15);
    int lcol = (lane < 16) ? 0 : 8;
    int l15 = lane & 15;
    int krow = l15 & 7;
    int kcsel = (l15 >> 3) * 8;

    float acc[8][4];
    #pragma unroll
    for (int i = 0; i < 8; i++)
        #pragma unroll
        for (int j = 0; j < 4; j++) acc[i][j] = 0.f;

    for (int k0 = 0; k0 < DMODEL; k0 += GK) {
        // load X chunk
        if (PRESPLIT) {
            #pragma unroll
            for (int i = 0; i < 4; i++) {
                int u = tid + i * 256;
                int pl = u >> 9;
                int r = (u >> 2) & 127;
                int c8 = (u & 3) * 8;
                const __nv_bfloat16* src = pl ? Xlo_g : Xhi_g;
                uint4 val = *(const uint4*)&src[(size_t)(bm + r) * DMODEL + k0 + c8];
                *(uint4*)&(pl ? Xl : Xh)[r * GSR + c8] = val;
            }
        } else {
            #pragma unroll
            for (int i = 0; i < 4; i++) {
                int u = tid + i * 256;
                int r = u >> 3;
                int c4 = (u & 7) * 4;
                float4 xv = *(const float4*)&Xf[(size_t)(bm + r) * DMODEL + k0 + c4];
                __nv_bfloat16 h0 = __float2bfloat16(xv.x), h1 = __float2bfloat16(xv.y);
                __nv_bfloat16 h2 = __float2bfloat16(xv.z), h3 = __float2bfloat16(xv.w);
                uint2 hv, lv;
                hv.x = pack_bf2(h0, h1); hv.y = pack_bf2(h2, h3);
                lv.x = pack_bf2(__float2bfloat16(xv.x - __bfloat162float(h0)),
                                __float2bfloat16(xv.y - __bfloat162float(h1)));
                lv.y = pack_bf2(__float2bfloat16(xv.z - __bfloat162float(h2)),
                                __float2bfloat16(xv.w - __bfloat162float(h3)));
                *(uint2*)&Xh[r * GSR + c4] = hv;
                *(uint2*)&Xl[r * GSR + c4] = lv;
            }
        }
        // load W chunk (fp32 -> hi/lo)
        #pragma unroll
        for (int i = 0; i < 2; i++) {
            int u = tid + i * 256;
            int r = u >> 3;
            int c4 = (u & 7) * 4;
            float4 wv = *(const float4*)&W[(size_t)(bn + r) * DMODEL + k0 + c4];
            __nv_bfloat16 h0 = __float2bfloat16(wv.x), h1 = __float2bfloat16(wv.y);
            __nv_bfloat16 h2 = __float2bfloat16(wv.z), h3 = __float2bfloat16(wv.w);
            uint2 hv, lv;
            hv.x = pack_bf2(h0, h1); hv.y = pack_bf2(h2, h3);
            lv.x = pack_bf2(__float2bfloat16(wv.x - __bfloat162float(h0)),
                            __float2bfloat16(wv.y - __bfloat162float(h1)));
            lv.y = pack_bf2(__float2bfloat16(wv.z - __bfloat162float(h2)),
                            __float2bfloat16(wv.w - __bfloat162float(h3)));
            *(uint2*)&Wh[r * GSR + c4] = hv;
            *(uint2*)&Wl[r * GSR + c4] = lv;
        }
        __syncthreads();

        #pragma unroll
        for (int ks = 0; ks < GK / 16; ks++) {
            uint32_t ah[4], al[4];
            ldsm_x4(ah, smaddr(&Xh[lrow * GSR + ks * 16 + lcol]));
            ldsm_x4(al, smaddr(&Xl[lrow * GSR + ks * 16 + lcol]));
            #pragma unroll
            for (int nt = 0; nt < 8; nt++) {
                uint32_t bh[2], bl[2];
                ldsm_x2(bh, smaddr(&Wh[(nt * 8 + krow) * GSR + ks * 16 + kcsel]));
                ldsm_x2(bl, smaddr(&Wl[(nt * 8 + krow) * GSR + ks * 16 + kcsel]));
                mma_bf16(acc[nt], ah, bh);
                mma_bf16(acc[nt], al, bh);
                mma_bf16(acc[nt], ah, bl);
            }
        }
        __syncthreads();
    }

    int r0 = bm + wid * 16 + g;
    #pragma unroll
    for (int nt = 0; nt < 8; nt++) {
        int c = bn + nt * 8 + 2 * t;
        float b0 = bias[c], b1 = bias[c + 1];
        float v00 = acc[nt][0] + b0, v01 = acc[nt][1] + b1;
        float v10 = acc[nt][2] + b0, v11 = acc[nt][3] + b1;
        if (OUTF32) {
            float* out = (float*)outp;
            float2 a; a.x = v00; a.y = v01;
            float2 b; b.x = v10; b.y = v11;
            *(float2*)&out[(size_t)r0 * DMODEL + c] = a;
            *(float2*)&out[(size_t)(r0 + 8) * DMODEL + c] = b;
        } else {
            uint32_t* out = (uint32_t*)outp;
            out[((size_t)r0 * DMODEL + c) >> 1] = pack_h2(v00, v01);
            out[((size_t)(r0 + 8) * DMODEL + c) >> 1] = pack_h2(v10, v11);
        }
    }
}

// ---------------- fp16 tensor-core flash attention, cp.async double-buffered ----------------
#define SROW 72   // fp16 row stride (144B): 16B-aligned, conflict-free LDSM
#define ATT_Q_ELEMS   (128 * SROW)
#define ATT_KV_ELEMS  (2 * 64 * SROW)
#define ATT_SMEM_BYTES ((ATT_Q_ELEMS + 2 * ATT_KV_ELEMS) * 2 + 2 * 256 * 4)

__global__ __launch_bounds__(256, 2) void attn_mma_kernel(
    const __half* __restrict__ Qg, const __half* __restrict__ Kg,
    const __half* __restrict__ Vg,
    __nv_bfloat16* __restrict__ AOhi, __nv_bfloat16* __restrict__ AOlo)
{
    extern __shared__ __half sm[];
    __half* Qs  = sm;
    __half* KV0 = sm + ATT_Q_ELEMS;
    __half* KV1 = KV0 + ATT_KV_ELEMS;
    uint32_t* Mb = (uint32_t*)(KV1 + ATT_KV_ELEMS);

    int tid = threadIdx.x;
    int lane = tid & 31, wid = tid >> 5;
    int g = lane >> 2, t = lane & 3;
    int h = blockIdx.y;
    int qbase = blockIdx.x * 128;
    int qr0 = wid * 16;
    int l15 = lane & 15;
    int krow = l15 & 7;
    int kcsel = (l15 >> 3) * 8;

    // ---- stage Q (128 x 64 fp16 = 1024 uint4) + mask words for tile 0 ----
    #pragma unroll
    for (int i = 0; i < 4; i++) {              // FIX: was i < 2 (only 64 rows loaded)
        int u = tid + i * 256;                 // u in [0,1024)
        int r = u >> 3;                        // rows 0..127
        int c8 = (u & 7) * 8;
        *(uint4*)&Qs[r * SROW + c8] =
            *(const uint4*)&Qg[(size_t)(qbase + r) * DMODEL + h * DHEAD + c8];
    }
    Mb[tid] = g_maskbits[(size_t)(qbase + (tid >> 1)) * (NTOK / 32) + (tid & 1)];

    // ---- cp.async: tile 0 -> KV0 ----
    {
        __half* dst = KV0;
        #pragma unroll
        for (int i = 0; i < 4; i++) {
            int u = tid + i * 256;
            int pl = u >> 9;
            int r = (u >> 3) & 63;
            int c8 = (u & 7) * 8;
            const __half* src = pl ? Vg : Kg;
            CP_ASYNC16(smaddr(&dst[pl * (64 * SROW) + r * SROW + c8]),
                       &src[(size_t)r * DMODEL + h * DHEAD + c8]);
        }
        CP_COMMIT();
    }
    __syncthreads();

    // ---- Q A-fragments ----
    uint32_t qf[4][4];
    {
        int lrow = qr0 + l15;
        int lcol = (lane < 16) ? 0 : 8;
        #pragma unroll
        for (int ks = 0; ks < 4; ks++)
            ldsm_x4(qf[ks], smaddr(&Qs[lrow * SROW + ks * 16 + lcol]));
    }
    __syncthreads();

    float o[8][4];
    #pragma unroll
    for (int i = 0; i < 8; i++)
        #pragma unroll
        for (int j = 0; j < 4; j++) o[i][j] = 0.f;
    float rmax0 = -3.0e38f, rmax1 = -3.0e38f, rsum0 = 0.f, rsum1 = 0.f;

    for (int kb = 0; kb < NTOK / 64; kb++) {
        if (kb + 1 < NTOK / 64) {
            __half* dst = ((kb + 1) & 1) ? KV1 : KV0;
            int kbase = (kb + 1) * 64;
            #pragma unroll
            for (int i = 0; i < 4; i++) {
                int u = tid + i * 256;
                int pl = u >> 9;
                int r = (u >> 3) & 63;
                int c8 = (u & 7) * 8;
                const __half* src = pl ? Vg : Kg;
                CP_ASYNC16(smaddr(&dst[pl * (64 * SROW) + r * SROW + c8]),
                           &src[(size_t)(kbase + r) * DMODEL + h * DHEAD + c8]);
            }
            CP_COMMIT();
            CP_WAIT1();
        } else {
            CP_WAIT0();
        }
        __syncthreads();

        __half* Ks = ((kb & 1) ? KV1 : KV0);
        __half* Vs = Ks + 64 * SROW;
        uint32_t* Mbc = Mb + (kb & 1) * 256;

        // ---- S = Q K^T ----
        float s[8][4];
        #pragma unroll
        for (int i = 0; i < 8; i++)
            #pragma unroll
            for (int j = 0; j < 4; j++) s[i][j] = 0.f;
        #pragma unroll
        for (int ks = 0; ks < 4; ks++) {
            #pragma unroll
            for (int nt = 0; nt < 8; nt++) {
                uint32_t bh[2];
                ldsm_x2(bh, smaddr(&Ks[(nt * 8 + krow) * SROW + ks * 16 + kcsel]));
                mma_f16(s[nt], qf[ks], bh);
            }
        }

        // ---- mask + scale + online softmax (fp32) ----
        uint32_t m00 = Mbc[(qr0 + g) * 2],     m01 = Mbc[(qr0 + g) * 2 + 1];
        uint32_t m10 = Mbc[(qr0 + g + 8) * 2], m11 = Mbc[(qr0 + g + 8) * 2 + 1];
        float mx0 = -3.0e38f, mx1 = -3.0e38f;
        #pragma unroll
        for (int nt = 0; nt < 8; nt++) {
            int c0 = nt * 8 + 2 * t;
            uint32_t w0 = (c0 < 32) ? m00 : m01;
            uint32_t w1 = (c0 < 32) ? m10 : m11;
            int sh = c0 & 31;
            s[nt][0] = ((w0 >> sh) & 1u)       ? -1.0e6f : s[nt][0] * SCALEF;
            s[nt][1] = ((w0 >> (sh + 1)) & 1u) ? -1.0e6f : s[nt][1] * SCALEF;
            s[nt][2] = ((w1 >> sh) & 1u)       ? -1.0e6f : s[nt][2] * SCALEF;
            s[nt][3] = ((w1 >> (sh + 1)) & 1u) ? -1.0e6f : s[nt][3] * SCALEF;
            mx0 = fmaxf(mx0, fmaxf(s[nt][0], s[nt][1]));
            mx1 = fmaxf(mx1, fmaxf(s[nt][2], s[nt][3]));
        }
        mx0 = fmaxf(mx0, __shfl_xor_sync(0xffffffffu, mx0, 1));
        mx0 = fmaxf(mx0, __shfl_xor_sync(0xffffffffu, mx0, 2));
        mx1 = fmaxf(mx1, __shfl_xor_sync(0xffffffffu, mx1, 1));
        mx1 = fmaxf(mx1, __shfl_xor_sync(0xffffffffu, mx1, 2));

        float nm0 = fmaxf(rmax0, mx0), nm1 = fmaxf(rmax1, mx1);
        float al0 = __expf(rmax0 - nm0), al1 = __expf(rmax1 - nm1);
        rmax0 = nm0; rmax1 = nm1;
        float ls0 = 0.f, ls1 = 0.f;
        #pragma unroll
        for (int nt = 0; nt < 8; nt++) {
            float p0 = __expf(s[nt][0] - nm0);
            float p1 = __expf(s[nt][1] - nm0);
            float p2 = __expf(s[nt][2] - nm1);
            float p3 = __expf(s[nt][3] - nm1);
            s[nt][0] = p0; s[nt][1] = p1; s[nt][2] = p2; s[nt][3] = p3;
            ls0 += p0 + p1; ls1 += p2 + p3;
        }
        ls0 += __shfl_xor_sync(0xffffffffu, ls0, 1);
        ls0 += __shfl_xor_sync(0xffffffffu, ls0, 2);
        ls1 += __shfl_xor_sync(0xffffffffu, ls1, 1);
        ls1 += __shfl_xor_sync(0xffffffffu, ls1, 2);
        rsum0 = rsum0 * al0 + ls0;
        rsum1 = rsum1 * al1 + ls1;
        #pragma unroll
        for (int nt = 0; nt < 8; nt++) {
            o[nt][0] *= al0; o[nt][1] *= al0; o[nt][2] *= al1; o[nt][3] *= al1;
        }

        // ---- O += P V ----
        #pragma unroll
        for (int ks = 0; ks < 4; ks++) {
            uint32_t pa[4];
            pa[0] = pack_h2(s[2 * ks][0],     s[2 * ks][1]);
            pa[1] = pack_h2(s[2 * ks][2],     s[2 * ks][3]);
            pa[2] = pack_h2(s[2 * ks + 1][0], s[2 * ks + 1][1]);
            pa[3] = pack_h2(s[2 * ks + 1][2], s[2 * ks + 1][3]);
            int vrow = ks * 16 + l15;
            #pragma unroll
            for (int ntd = 0; ntd < 8; ntd++) {
                uint32_t vh[2];
                ldsm_x2t(vh, smaddr(&Vs[vrow * SROW + ntd * 8]));
                mma_f16(o[ntd], pa, vh);
            }
        }

        if (kb + 1 < NTOK / 64)
            Mb[((kb + 1) & 1) * 256 + tid] =
                g_maskbits[(size_t)(qbase + (tid >> 1)) * (NTOK / 32) + (kb + 1) * 2 + (tid & 1)];
        __syncthreads();
    }

    // ---- epilogue: write hi/lo bf16 planes ----
    float inv0 = 1.0f / rsum0, inv1 = 1.0f / rsum1;
    int r0 = qbase + qr0 + g;
    #pragma unroll
    for (int nt = 0; nt < 8; nt++) {
        int c = h * DHEAD + nt * 8 + 2 * t;
        float x0 = o[nt][0] * inv0, x1 = o[nt][1] * inv0;
        float y0 = o[nt][2] * inv1, y1 = o[nt][3] * inv1;
        __nv_bfloat16 hx0 = __float2bfloat16(x0), hx1 = __float2bfloat16(x1);
        __nv_bfloat16 hy0 = __float2bfloat16(y0), hy1 = __float2bfloat16(y1);
        *(uint32_t*)&AOhi[(size_t)r0 * DMODEL + c] = pack_bf2(hx0, hx1);
        *(uint32_t*)&AOlo[(size_t)r0 * DMODEL + c] =
            pack_bf2(__float2bfloat16(x0 - __bfloat162float(hx0)),
                     __float2bfloat16(x1 - __bfloat162float(hx1)));
        *(uint32_t*)&AOhi[(size_t)(r0 + 8) * DMODEL + c] = pack_bf2(hy0, hy1);
        *(uint32_t*)&AOlo[(size_t)(r0 + 8) * DMODEL + c] =
            pack_bf2(__float2bfloat16(y0 - __bfloat162float(hy0)),
                     __float2bfloat16(y1 - __bfloat162float(hy1)));
    }
}

// ---------------- launch ----------------
extern "C" void kernel_launch(void* const* d_in, const int* in_sizes, int n_in,
                              void* d_out, int out_size) {
    const float* q    = (const float*)d_in[0];
    const float* k    = (const float*)d_in[1];
    const float* v    = (const float*)d_in[2];
    const void*  mask = d_in[3];
    const float* wq_w = (const float*)d_in[4];
    const float* wq_b = (const float*)d_in[5];
    const float* wk_w = (const float*)d_in[6];
    const float* wk_b = (const float*)d_in[7];
    const float* wv_w = (const float*)d_in[8];
    const float* wv_b = (const float*)d_in[9];
    const float* wo_w = (const float*)d_in[10];
    const float* wo_b = (const float*)d_in[11];
    float* out = (float*)d_out;

    __half *q16, *k16, *v16;
    __nv_bfloat16 *aohi, *aolo;
    cudaGetSymbolAddress((void**)&q16,  g_q16);
    cudaGetSymbolAddress((void**)&k16,  g_k16);
    cudaGetSymbolAddress((void**)&v16,  g_v16);
    cudaGetSymbolAddress((void**)&aohi, g_aohi);
    cudaGetSymbolAddress((void**)&aolo, g_aolo);

    cudaFuncSetAttribute(attn_mma_kernel, cudaFuncAttributeMaxDynamicSharedMemorySize,
                         ATT_SMEM_BYTES);

    // mask -> bitmask
    detect_mask_kernel<<<1, 256>>>((const unsigned char*)mask);
    pack_mask_kernel<<<(NTOK * NTOK / 32 + 255) / 256, 256>>>(mask);

    // projections (split-bf16 tensor GEMM, fp16 planes out)
    dim3 ggrid(DMODEL / 64, NTOK / 128);
    gemm_tc<false, false><<<ggrid, 256>>>(q, nullptr, nullptr, wq_w, wq_b, (void*)q16);
    gemm_tc<false, false><<<ggrid, 256>>>(k, nullptr, nullptr, wk_w, wk_b, (void*)k16);
    gemm_tc<false, false><<<ggrid, 256>>>(v, nullptr, nullptr, wv_w, wv_b, (void*)v16);

    // fp16 tensor-core attention (writes pre-split bf16 hi/lo)
    attn_mma_kernel<<<dim3(NTOK / 128, NHEADS), 256, ATT_SMEM_BYTES>>>(
        q16, k16, v16, aohi, aolo);

    // output projection (pre-split input, fp32 out)
    gemm_tc<true, true><<<ggrid, 256>>>(nullptr, aohi, aolo, wo_w, wo_b, out);
}

// round 10
// speedup vs baseline: 11.2517x; 1.1856x over previous
#include <cuda_runtime.h>
#include <cuda_bf16.h>
#include <cuda_fp16.h>
#include <cstdint>

#define NTOK   4096
#define DMODEL 512
#define NHEADS 8
#define DHEAD  64
#define SCALEF 0.125f           // 1/sqrt(64)
#define C2F    0.18033688f      // SCALEF * log2(e)

// ---------------- scratch (static device globals; no allocation) ----------------
__device__ __half g_q16[NTOK * DMODEL];
__device__ __half g_k16[NTOK * DMODEL];
__device__ __half g_v16[NTOK * DMODEL];
__device__ __nv_bfloat16 g_aohi[NTOK * DMODEL];
__device__ __nv_bfloat16 g_aolo[NTOK * DMODEL];
__device__ unsigned int g_maskbits[NTOK * (NTOK / 32)];
__device__ int g_mask_is_u8;

// ---------------- mask dtype detection + bit-packing ----------------
__global__ void detect_mask_kernel(const unsigned char* __restrict__ mask) {
    __shared__ int cnt[256];
    int c = 0;
    for (int i = threadIdx.x; i < 16384; i += 256) c += (mask[i] != 0);
    cnt[threadIdx.x] = c;
    __syncthreads();
    for (int s = 128; s > 0; s >>= 1) {
        if (threadIdx.x < s) cnt[threadIdx.x] += cnt[threadIdx.x + s];
        __syncthreads();
    }
    if (threadIdx.x == 0) g_mask_is_u8 = (cnt[0] > 1024) ? 1 : 0;
}

__global__ void pack_mask_kernel(const void* __restrict__ maskp) {
    int w = blockIdx.x * blockDim.x + threadIdx.x;
    if (w >= NTOK * NTOK / 32) return;
    unsigned int bits = 0;
    if (g_mask_is_u8) {
        const unsigned char* m = (const unsigned char*)maskp + (size_t)w * 32;
        #pragma unroll
        for (int i = 0; i < 32; i++) bits |= (m[i] ? 1u : 0u) << i;
    } else {
        const unsigned int* m = (const unsigned int*)maskp + (size_t)w * 32;
        #pragma unroll
        for (int i = 0; i < 32; i++) bits |= (m[i] ? 1u : 0u) << i;
    }
    g_maskbits[w] = bits;
}

// ---------------- MMA / LDSM helpers ----------------
__device__ __forceinline__ uint32_t smaddr(const void* p) {
    return (uint32_t)__cvta_generic_to_shared(p);
}
__device__ __forceinline__ void ldsm_x4(uint32_t* r, uint32_t a) {
    asm volatile("ldmatrix.sync.aligned.m8n8.x4.shared.b16 {%0,%1,%2,%3}, [%4];"
                 : "=r"(r[0]), "=r"(r[1]), "=r"(r[2]), "=r"(r[3]) : "r"(a));
}
__device__ __forceinline__ void ldsm_x2(uint32_t* r, uint32_t a) {
    asm volatile("ldmatrix.sync.aligned.m8n8.x2.shared.b16 {%0,%1}, [%2];"
                 : "=r"(r[0]), "=r"(r[1]) : "r"(a));
}
__device__ __forceinline__ void ldsm_x2t(uint32_t* r, uint32_t a) {
    asm volatile("ldmatrix.sync.aligned.m8n8.x2.trans.shared.b16 {%0,%1}, [%2];"
                 : "=r"(r[0]), "=r"(r[1]) : "r"(a));
}
__device__ __forceinline__ void mma_bf16(float* d, const uint32_t* a, const uint32_t* b) {
    asm volatile("mma.sync.aligned.m16n8k16.row.col.f32.bf16.bf16.f32 "
                 "{%0,%1,%2,%3}, {%4,%5,%6,%7}, {%8,%9}, {%0,%1,%2,%3};"
                 : "+f"(d[0]), "+f"(d[1]), "+f"(d[2]), "+f"(d[3])
                 : "r"(a[0]), "r"(a[1]), "r"(a[2]), "r"(a[3]), "r"(b[0]), "r"(b[1]));
}
__device__ __forceinline__ void mma_f16(float* d, const uint32_t* a, const uint32_t* b) {
    asm volatile("mma.sync.aligned.m16n8k16.row.col.f32.f16.f16.f32 "
                 "{%0,%1,%2,%3}, {%4,%5,%6,%7}, {%8,%9}, {%0,%1,%2,%3};"
                 : "+f"(d[0]), "+f"(d[1]), "+f"(d[2]), "+f"(d[3])
                 : "r"(a[0]), "r"(a[1]), "r"(a[2]), "r"(a[3]), "r"(b[0]), "r"(b[1]));
}
__device__ __forceinline__ uint32_t pack_h2(float x, float y) {
    __half2 p = __floats2half2_rn(x, y);
    return *reinterpret_cast<uint32_t*>(&p);
}
__device__ __forceinline__ uint32_t pack_bf2(__nv_bfloat16 a, __nv_bfloat16 b) {
    return (uint32_t)__bfloat16_as_ushort(a) | ((uint32_t)__bfloat16_as_ushort(b) << 16);
}
__device__ __forceinline__ float ex2f(float x) {
    float r;
    asm("ex2.approx.ftz.f32 %0, %1;" : "=f"(r) : "f"(x));
    return r;
}

#define CP_ASYNC16(dst, src) \
    asm volatile("cp.async.cg.shared.global [%0], [%1], 16;" :: "r"(dst), "l"(src))
#define CP_COMMIT() asm volatile("cp.async.commit_group;")
#define CP_WAIT0()  asm volatile("cp.async.wait_group 0;")

// ---------------- split-bf16 tensor GEMM: C = X[M,K] @ W[N,K]^T + b ----------------
#define GK 32      // k-chunk
#define GSR 40     // smem row stride (bf16), 80B -> 16B-aligned + conflict-free

// shared MMA mainloop body over staged smem tiles
__device__ __forceinline__ void gemm_mma_chunk(
    const __nv_bfloat16* Xh, const __nv_bfloat16* Xl,
    const __nv_bfloat16* Wh, const __nv_bfloat16* Wl,
    int lrow, int lcol, int krow, int kcsel, float acc[8][4])
{
    #pragma unroll
    for (int ks = 0; ks < GK / 16; ks++) {
        uint32_t ah[4], al[4];
        ldsm_x4(ah, smaddr(&Xh[lrow * GSR + ks * 16 + lcol]));
        ldsm_x4(al, smaddr(&Xl[lrow * GSR + ks * 16 + lcol]));
        #pragma unroll
        for (int nt = 0; nt < 8; nt++) {
            uint32_t bh[2], bl[2];
            ldsm_x2(bh, smaddr(&Wh[(nt * 8 + krow) * GSR + ks * 16 + kcsel]));
            ldsm_x2(bl, smaddr(&Wl[(nt * 8 + krow) * GSR + ks * 16 + kcsel]));
            mma_bf16(acc[nt], ah, bh);
            mma_bf16(acc[nt], al, bh);
            mma_bf16(acc[nt], ah, bl);
        }
    }
}

__device__ __forceinline__ void split2(float x, float y, uint32_t& hv, uint32_t& lv) {
    __nv_bfloat16 h0 = __float2bfloat16(x), h1 = __float2bfloat16(y);
    hv = pack_bf2(h0, h1);
    lv = pack_bf2(__float2bfloat16(x - __bfloat162float(h0)),
                  __float2bfloat16(y - __bfloat162float(h1)));
}

// fused Q/K/V projection: grid (8, 32, 3); fp32 in, fp16 out; register-prefetched
__global__ __launch_bounds__(256, 2) void gemm_qkv(
    const float* __restrict__ Xq, const float* __restrict__ Xk, const float* __restrict__ Xv,
    const float* __restrict__ Wq, const float* __restrict__ Wk, const float* __restrict__ Wv,
    const float* __restrict__ Bq, const float* __restrict__ Bk, const float* __restrict__ Bv,
    __half* __restrict__ Oq, __half* __restrict__ Ok, __half* __restrict__ Ov)
{
    __shared__ __nv_bfloat16 Xh[128 * GSR], Xl[128 * GSR];
    __shared__ __nv_bfloat16 Wh[64 * GSR],  Wl[64 * GSR];

    int z = blockIdx.z;
    const float* X = (z == 0) ? Xq : (z == 1) ? Xk : Xv;
    const float* W = (z == 0) ? Wq : (z == 1) ? Wk : Wv;
    const float* B = (z == 0) ? Bq : (z == 1) ? Bk : Bv;
    __half* Out    = (z == 0) ? Oq : (z == 1) ? Ok : Ov;

    int tid = threadIdx.x;
    int lane = tid & 31, wid = tid >> 5;
    int g = lane >> 2, t = lane & 3;
    int bm = blockIdx.y * 128, bn = blockIdx.x * 64;
    int lrow = wid * 16 + (lane & 15);
    int lcol = (lane < 16) ? 0 : 8;
    int l15 = lane & 15;
    int krow = l15 & 7;
    int kcsel = (l15 >> 3) * 8;

    float acc[8][4];
    #pragma unroll
    for (int i = 0; i < 8; i++)
        #pragma unroll
        for (int j = 0; j < 4; j++) acc[i][j] = 0.f;

    // prefetch registers for chunk 0
    float4 xr[4], wr[2];
    #pragma unroll
    for (int i = 0; i < 4; i++) {
        int u = tid + i * 256;
        xr[i] = *(const float4*)&X[(size_t)(bm + (u >> 3)) * DMODEL + (u & 7) * 4];
    }
    #pragma unroll
    for (int i = 0; i < 2; i++) {
        int u = tid + i * 256;
        wr[i] = *(const float4*)&W[(size_t)(bn + (u >> 3)) * DMODEL + (u & 7) * 4];
    }

    for (int k0 = 0; k0 < DMODEL; k0 += GK) {
        // STS (convert prefetched registers)
        #pragma unroll
        for (int i = 0; i < 4; i++) {
            int u = tid + i * 256;
            int r = u >> 3, c4 = (u & 7) * 4;
            uint2 hv, lv;
            split2(xr[i].x, xr[i].y, hv.x, lv.x);
            split2(xr[i].z, xr[i].w, hv.y, lv.y);
            *(uint2*)&Xh[r * GSR + c4] = hv;
            *(uint2*)&Xl[r * GSR + c4] = lv;
        }
        #pragma unroll
        for (int i = 0; i < 2; i++) {
            int u = tid + i * 256;
            int r = u >> 3, c4 = (u & 7) * 4;
            uint2 hv, lv;
            split2(wr[i].x, wr[i].y, hv.x, lv.x);
            split2(wr[i].z, wr[i].w, hv.y, lv.y);
            *(uint2*)&Wh[r * GSR + c4] = hv;
            *(uint2*)&Wl[r * GSR + c4] = lv;
        }
        __syncthreads();

        // prefetch next chunk (LDG latency hidden behind MMAs)
        if (k0 + GK < DMODEL) {
            #pragma unroll
            for (int i = 0; i < 4; i++) {
                int u = tid + i * 256;
                xr[i] = *(const float4*)&X[(size_t)(bm + (u >> 3)) * DMODEL + k0 + GK + (u & 7) * 4];
            }
            #pragma unroll
            for (int i = 0; i < 2; i++) {
                int u = tid + i * 256;
                wr[i] = *(const float4*)&W[(size_t)(bn + (u >> 3)) * DMODEL + k0 + GK + (u & 7) * 4];
            }
        }

        gemm_mma_chunk(Xh, Xl, Wh, Wl, lrow, lcol, krow, kcsel, acc);
        __syncthreads();
    }

    int r0 = bm + wid * 16 + g;
    #pragma unroll
    for (int nt = 0; nt < 8; nt++) {
        int c = bn + nt * 8 + 2 * t;
        float b0 = B[c], b1 = B[c + 1];
        uint32_t* out = (uint32_t*)Out;
        out[((size_t)r0 * DMODEL + c) >> 1] = pack_h2(acc[nt][0] + b0, acc[nt][1] + b1);
        out[((size_t)(r0 + 8) * DMODEL + c) >> 1] = pack_h2(acc[nt][2] + b0, acc[nt][3] + b1);
    }
}

// output projection: pre-split bf16 X planes, fp32 out; register-prefetched
__global__ __launch_bounds__(256, 2) void gemm_o(
    const __nv_bfloat16* __restrict__ Xhi_g, const __nv_bfloat16* __restrict__ Xlo_g,
    const float* __restrict__ W, const float* __restrict__ B, float* __restrict__ Out)
{
    __shared__ __nv_bfloat16 Xh[128 * GSR], Xl[128 * GSR];
    __shared__ __nv_bfloat16 Wh[64 * GSR],  Wl[64 * GSR];

    int tid = threadIdx.x;
    int lane = tid & 31, wid = tid >> 5;
    int g = lane >> 2, t = lane & 3;
    int bm = blockIdx.y * 128, bn = blockIdx.x * 64;
    int lrow = wid * 16 + (lane & 15);
    int lcol = (lane < 16) ? 0 : 8;
    int l15 = lane & 15;
    int krow = l15 & 7;
    int kcsel = (l15 >> 3) * 8;

    float acc[8][4];
    #pragma unroll
    for (int i = 0; i < 8; i++)
        #pragma unroll
        for (int j = 0; j < 4; j++) acc[i][j] = 0.f;

    uint4 xr[4];      // 2 planes x 2 uint4
    float4 wr[2];
    #pragma unroll
    for (int i = 0; i < 4; i++) {
        int u = tid + i * 256;
        const __nv_bfloat16* src = (u >> 9) ? Xlo_g : Xhi_g;
        int r = (u >> 2) & 127, c8 = (u & 3) * 8;
        xr[i] = *(const uint4*)&src[(size_t)(bm + r) * DMODEL + c8];
    }
    #pragma unroll
    for (int i = 0; i < 2; i++) {
        int u = tid + i * 256;
        wr[i] = *(const float4*)&W[(size_t)(bn + (u >> 3)) * DMODEL + (u & 7) * 4];
    }

    for (int k0 = 0; k0 < DMODEL; k0 += GK) {
        #pragma unroll
        for (int i = 0; i < 4; i++) {
            int u = tid + i * 256;
            int pl = u >> 9;
            int r = (u >> 2) & 127, c8 = (u & 3) * 8;
            *(uint4*)&(pl ? Xl : Xh)[r * GSR + c8] = xr[i];
        }
        #pragma unroll
        for (int i = 0; i < 2; i++) {
            int u = tid + i * 256;
            int r = u >> 3, c4 = (u & 7) * 4;
            uint2 hv, lv;
            split2(wr[i].x, wr[i].y, hv.x, lv.x);
            split2(wr[i].z, wr[i].w, hv.y, lv.y);
            *(uint2*)&Wh[r * GSR + c4] = hv;
            *(uint2*)&Wl[r * GSR + c4] = lv;
        }
        __syncthreads();

        if (k0 + GK < DMODEL) {
            #pragma unroll
            for (int i = 0; i < 4; i++) {
                int u = tid + i * 256;
                const __nv_bfloat16* src = (u >> 9) ? Xlo_g : Xhi_g;
                int r = (u >> 2) & 127, c8 = (u & 3) * 8;
                xr[i] = *(const uint4*)&src[(size_t)(bm + r) * DMODEL + k0 + GK + c8];
            }
            #pragma unroll
            for (int i = 0; i < 2; i++) {
                int u = tid + i * 256;
                wr[i] = *(const float4*)&W[(size_t)(bn + (u >> 3)) * DMODEL + k0 + GK + (u & 7) * 4];
            }
        }

        gemm_mma_chunk(Xh, Xl, Wh, Wl, lrow, lcol, krow, kcsel, acc);
        __syncthreads();
    }

    int r0 = bm + wid * 16 + g;
    #pragma unroll
    for (int nt = 0; nt < 8; nt++) {
        int c = bn + nt * 8 + 2 * t;
        float b0 = B[c], b1 = B[c + 1];
        float2 a; a.x = acc[nt][0] + b0; a.y = acc[nt][1] + b1;
        float2 b; b.x = acc[nt][2] + b0; b.y = acc[nt][3] + b1;
        *(float2*)&Out[(size_t)r0 * DMODEL + c] = a;
        *(float2*)&Out[(size_t)(r0 + 8) * DMODEL + c] = b;
    }
}

// ---------------- fp16 tensor-core flash attention, cp.async double-buffered ----------------
#define SROW 72
#define ATT_Q_ELEMS   (128 * SROW)
#define ATT_KV_ELEMS  (2 * 64 * SROW)
#define ATT_SMEM_BYTES ((ATT_Q_ELEMS + 2 * ATT_KV_ELEMS) * 2 + 2 * 256 * 4)

__global__ __launch_bounds__(256, 2) void attn_mma_kernel(
    const __half* __restrict__ Qg, const __half* __restrict__ Kg,
    const __half* __restrict__ Vg,
    __nv_bfloat16* __restrict__ AOhi, __nv_bfloat16* __restrict__ AOlo)
{
    extern __shared__ __half sm[];
    __half* Qs  = sm;
    __half* KV0 = sm + ATT_Q_ELEMS;
    __half* KV1 = KV0 + ATT_KV_ELEMS;
    uint32_t* Mb = (uint32_t*)(KV1 + ATT_KV_ELEMS);

    int tid = threadIdx.x;
    int lane = tid & 31, wid = tid >> 5;
    int g = lane >> 2, t = lane & 3;
    int h = blockIdx.y;
    int qbase = blockIdx.x * 128;
    int qr0 = wid * 16;
    int l15 = lane & 15;
    int krow = l15 & 7;
    int kcsel = (l15 >> 3) * 8;

    // ---- prologue: stage Q (1024 uint4), Mb slot 0, cp.async tile 0 ----
    #pragma unroll
    for (int i = 0; i < 4; i++) {
        int u = tid + i * 256;
        int r = u >> 3;
        int c8 = (u & 7) * 8;
        *(uint4*)&Qs[r * SROW + c8] =
            *(const uint4*)&Qg[(size_t)(qbase + r) * DMODEL + h * DHEAD + c8];
    }
    Mb[tid] = g_maskbits[(size_t)(qbase + (tid >> 1)) * (NTOK / 32) + (tid & 1)];
    {
        #pragma unroll
        for (int i = 0; i < 4; i++) {
            int u = tid + i * 256;
            int pl = u >> 9;
            int r = (u >> 3) & 63;
            int c8 = (u & 7) * 8;
            const __half* src = pl ? Vg : Kg;
            CP_ASYNC16(smaddr(&KV0[pl * (64 * SROW) + r * SROW + c8]),
                       &src[(size_t)r * DMODEL + h * DHEAD + c8]);
        }
        CP_COMMIT();
    }
    __syncthreads();

    // ---- Q A-fragments (Qs never overwritten) ----
    uint32_t qf[4][4];
    {
        int lrow = qr0 + l15;
        int lcol = (lane < 16) ? 0 : 8;
        #pragma unroll
        for (int ks = 0; ks < 4; ks++)
            ldsm_x4(qf[ks], smaddr(&Qs[lrow * SROW + ks * 16 + lcol]));
    }

    float o[8][4];
    #pragma unroll
    for (int i = 0; i < 8; i++)
        #pragma unroll
        for (int j = 0; j < 4; j++) o[i][j] = 0.f;
    float rmax0 = -3.0e38f, rmax1 = -3.0e38f, rsum0 = 0.f, rsum1 = 0.f;

    for (int kb = 0; kb < NTOK / 64; kb++) {
        CP_WAIT0();          // this tile's cp.async landed (issuing thread's view)
        __syncthreads();     // all warps: prev compute done + arrivals visible

        // issue next tile into the other buffer + next mask slot
        if (kb + 1 < NTOK / 64) {
            Mb[((kb + 1) & 1) * 256 + tid] =
                g_maskbits[(size_t)(qbase + (tid >> 1)) * (NTOK / 32) + (kb + 1) * 2 + (tid & 1)];
            __half* dst = ((kb + 1) & 1) ? KV1 : KV0;
            int kbase = (kb + 1) * 64;
            #pragma unroll
            for (int i = 0; i < 4; i++) {
                int u = tid + i * 256;
                int pl = u >> 9;
                int r = (u >> 3) & 63;
                int c8 = (u & 7) * 8;
                const __half* src = pl ? Vg : Kg;
                CP_ASYNC16(smaddr(&dst[pl * (64 * SROW) + r * SROW + c8]),
                           &src[(size_t)(kbase + r) * DMODEL + h * DHEAD + c8]);
            }
            CP_COMMIT();
        }

        __half* Ks = ((kb & 1) ? KV1 : KV0);
        __half* Vs = Ks + 64 * SROW;
        uint32_t* Mbc = Mb + (kb & 1) * 256;

        // ---- S = Q K^T ----
        float s[8][4];
        #pragma unroll
        for (int i = 0; i < 8; i++)
            #pragma unroll
            for (int j = 0; j < 4; j++) s[i][j] = 0.f;
        #pragma unroll
        for (int ks = 0; ks < 4; ks++) {
            #pragma unroll
            for (int nt = 0; nt < 8; nt++) {
                uint32_t bh[2];
                ldsm_x2(bh, smaddr(&Ks[(nt * 8 + krow) * SROW + ks * 16 + kcsel]));
                mma_f16(s[nt], qf[ks], bh);
            }
        }

        // ---- mask + scale (log2 domain) + online softmax via ex2 ----
        uint32_t m00 = Mbc[(qr0 + g) * 2],     m01 = Mbc[(qr0 + g) * 2 + 1];
        uint32_t m10 = Mbc[(qr0 + g + 8) * 2], m11 = Mbc[(qr0 + g + 8) * 2 + 1];
        float mx0 = -3.0e38f, mx1 = -3.0e38f;
        #pragma unroll
        for (int nt = 0; nt < 8; nt++) {
            int c0 = nt * 8 + 2 * t;
            uint32_t w0 = (c0 < 32) ? m00 : m01;
            uint32_t w1 = (c0 < 32) ? m10 : m11;
            int sh = c0 & 31;
            s[nt][0] = ((w0 >> sh) & 1u)       ? -2.0e6f : s[nt][0] * C2F;
            s[nt][1] = ((w0 >> (sh + 1)) & 1u) ? -2.0e6f : s[nt][1] * C2F;
            s[nt][2] = ((w1 >> sh) & 1u)       ? -2.0e6f : s[nt][2] * C2F;
            s[nt][3] = ((w1 >> (sh + 1)) & 1u) ? -2.0e6f : s[nt][3] * C2F;
            mx0 = fmaxf(mx0, fmaxf(s[nt][0], s[nt][1]));
            mx1 = fmaxf(mx1, fmaxf(s[nt][2], s[nt][3]));
        }
        mx0 = fmaxf(mx0, __shfl_xor_sync(0xffffffffu, mx0, 1));
        mx0 = fmaxf(mx0, __shfl_xor_sync(0xffffffffu, mx0, 2));
        mx1 = fmaxf(mx1, __shfl_xor_sync(0xffffffffu, mx1, 1));
        mx1 = fmaxf(mx1, __shfl_xor_sync(0xffffffffu, mx1, 2));

        float nm0 = fmaxf(rmax0, mx0), nm1 = fmaxf(rmax1, mx1);
        float al0 = ex2f(rmax0 - nm0), al1 = ex2f(rmax1 - nm1);
        rmax0 = nm0; rmax1 = nm1;
        float ls0 = 0.f, ls1 = 0.f;
        #pragma unroll
        for (int nt = 0; nt < 8; nt++) {
            float p0 = ex2f(s[nt][0] - nm0);
            float p1 = ex2f(s[nt][1] - nm0);
            float p2 = ex2f(s[nt][2] - nm1);
            float p3 = ex2f(s[nt][3] - nm1);
            s[nt][0] = p0; s[nt][1] = p1; s[nt][2] = p2; s[nt][3] = p3;
            ls0 += p0 + p1; ls1 += p2 + p3;
        }
        ls0 += __shfl_xor_sync(0xffffffffu, ls0, 1);
        ls0 += __shfl_xor_sync(0xffffffffu, ls0, 2);
        ls1 += __shfl_xor_sync(0xffffffffu, ls1, 1);
        ls1 += __shfl_xor_sync(0xffffffffu, ls1, 2);
        rsum0 = rsum0 * al0 + ls0;
        rsum1 = rsum1 * al1 + ls1;
        #pragma unroll
        for (int nt = 0; nt < 8; nt++) {
            o[nt][0] *= al0; o[nt][1] *= al0; o[nt][2] *= al1; o[nt][3] *= al1;
        }

        // ---- O += P V ----
        #pragma unroll
        for (int ks = 0; ks < 4; ks++) {
            uint32_t pa[4];
            pa[0] = pack_h2(s[2 * ks][0],     s[2 * ks][1]);
            pa[1] = pack_h2(s[2 * ks][2],     s[2 * ks][3]);
            pa[2] = pack_h2(s[2 * ks + 1][0], s[2 * ks + 1][1]);
            pa[3] = pack_h2(s[2 * ks + 1][2], s[2 * ks + 1][3]);
            int vrow = ks * 16 + l15;
            #pragma unroll
            for (int ntd = 0; ntd < 8; ntd++) {
                uint32_t vh[2];
                ldsm_x2t(vh, smaddr(&Vs[vrow * SROW + ntd * 8]));
                mma_f16(o[ntd], pa, vh);
            }
        }
    }

    // ---- epilogue: write hi/lo bf16 planes ----
    float inv0 = 1.0f / rsum0, inv1 = 1.0f / rsum1;
    int r0 = qbase + qr0 + g;
    #pragma unroll
    for (int nt = 0; nt < 8; nt++) {
        int c = h * DHEAD + nt * 8 + 2 * t;
        float x0 = o[nt][0] * inv0, x1 = o[nt][1] * inv0;
        float y0 = o[nt][2] * inv1, y1 = o[nt][3] * inv1;
        __nv_bfloat16 hx0 = __float2bfloat16(x0), hx1 = __float2bfloat16(x1);
        __nv_bfloat16 hy0 = __float2bfloat16(y0), hy1 = __float2bfloat16(y1);
        *(uint32_t*)&AOhi[(size_t)r0 * DMODEL + c] = pack_bf2(hx0, hx1);
        *(uint32_t*)&AOlo[(size_t)r0 * DMODEL + c] =
            pack_bf2(__float2bfloat16(x0 - __bfloat162float(hx0)),
                     __float2bfloat16(x1 - __bfloat162float(hx1)));
        *(uint32_t*)&AOhi[(size_t)(r0 + 8) * DMODEL + c] = pack_bf2(hy0, hy1);
        *(uint32_t*)&AOlo[(size_t)(r0 + 8) * DMODEL + c] =
            pack_bf2(__float2bfloat16(y0 - __bfloat162float(hy0)),
                     __float2bfloat16(y1 - __bfloat162float(hy1)));
    }
}

// ---------------- launch ----------------
extern "C" void kernel_launch(void* const* d_in, const int* in_sizes, int n_in,
                              void* d_out, int out_size) {
    const float* q    = (const float*)d_in[0];
    const float* k    = (const float*)d_in[1];
    const float* v    = (const float*)d_in[2];
    const void*  mask = d_in[3];
    const float* wq_w = (const float*)d_in[4];
    const float* wq_b = (const float*)d_in[5];
    const float* wk_w = (const float*)d_in[6];
    const float* wk_b = (const float*)d_in[7];
    const float* wv_w = (const float*)d_in[8];
    const float* wv_b = (const float*)d_in[9];
    const float* wo_w = (const float*)d_in[10];
    const float* wo_b = (const float*)d_in[11];
    float* out = (float*)d_out;

    __half *q16, *k16, *v16;
    __nv_bfloat16 *aohi, *aolo;
    cudaGetSymbolAddress((void**)&q16,  g_q16);
    cudaGetSymbolAddress((void**)&k16,  g_k16);
    cudaGetSymbolAddress((void**)&v16,  g_v16);
    cudaGetSymbolAddress((void**)&aohi, g_aohi);
    cudaGetSymbolAddress((void**)&aolo, g_aolo);

    cudaFuncSetAttribute(attn_mma_kernel, cudaFuncAttributeMaxDynamicSharedMemorySize,
                         ATT_SMEM_BYTES);

    // mask -> bitmask
    detect_mask_kernel<<<1, 256>>>((const unsigned char*)mask);
    pack_mask_kernel<<<(NTOK * NTOK / 32 + 255) / 256, 256>>>(mask);

    // fused Q/K/V projections (split-bf16 tensor GEMM, fp16 out)
    gemm_qkv<<<dim3(DMODEL / 64, NTOK / 128, 3), 256>>>(
        q, k, v, wq_w, wk_w, wv_w, wq_b, wk_b, wv_b, q16, k16, v16);

    // fp16 tensor-core attention (writes pre-split bf16 hi/lo)
    attn_mma_kernel<<<dim3(NTOK / 128, NHEADS), 256, ATT_SMEM_BYTES>>>(
        q16, k16, v16, aohi, aolo);

    // output projection
    gemm_o<<<dim3(DMODEL / 64, NTOK / 128), 256>>>(aohi, aolo, wo_w, wo_b, out);
}